// round 12
// baseline (speedup 1.0000x reference)
#include <cuda_runtime.h>

#define N_NODES 100000
#define N_EDGES 800000
#define DIN 16
#define H 128
#define OUTD 3
#define SLOPE 0.01f

typedef unsigned long long u64;

// ---------------- packed f32x2 helpers (sm_103a) ----------------
__device__ __forceinline__ u64 pk2(float lo, float hi) {
    u64 r; asm("mov.b64 %0, {%1, %2};" : "=l"(r) : "f"(lo), "f"(hi)); return r;
}
__device__ __forceinline__ void upk2(float& lo, float& hi, u64 v) {
    asm("mov.b64 {%0, %1}, %2;" : "=f"(lo), "=f"(hi) : "l"(v));
}
__device__ __forceinline__ void fma2(u64& d, u64 a, u64 b) {
    asm("fma.rn.f32x2 %0, %1, %2, %0;" : "+l"(d) : "l"(a), "l"(b));
}

// ---------------- scratch (no allocations; zero-initialized at load) -------
// INVARIANT: g_deg and g_acc are all-zero at kernel_launch entry; k_final
// restores this before finishing, so graph replays are deterministic.
__device__ __align__(16) float  g_deg[N_NODES];       // in-degree (float)
__device__ __align__(16) float  g_dinv[N_NODES];      // rsqrt(deg+1)
__device__ __align__(16) float4 g_z4 [N_NODES];       // p = (dinv*z, dinv)
__device__ __align__(16) float4 g_acc[N_NODES];       // edge accumulator (both passes)
__device__ __align__(16) float4 g_z14[N_NODES];       // q = (dinv*z1, 0)
__device__ __align__(16) float  g_a1 [N_NODES];       // (A·1)_d
__device__ __align__(16) float  g_Wc [H * OUTD];      // W1 @ W2 @ W_out
__device__ float g_v[OUTD];                           // b1 @ W2 @ W_out
__device__ float g_c[OUTD];                           // b2 @ W_out + b_out

// resolved by k_count block 0 (visible to dependent kernels after their
// cudaGridDependencySynchronize / stream order)
__device__ const void*  g_ei_ptr;                     // edge_index [2, E]
__device__ int          g_ei64;                       // 1 = int64 elements, 0 = int32
__device__ const float* g_feat_p;                     // feature    [N, DIN]

__device__ __forceinline__ int2 load_edge_g(int e) {
    if (g_ei64) {
        const long long* p = (const long long*)g_ei_ptr;
        return make_int2((int)p[e], (int)p[N_EDGES + e]);
    } else {
        const int* p = (const int*)g_ei_ptr;
        return make_int2(p[e], p[N_EDGES + e]);
    }
}

// ---------------- K1: per-block ident + degree count + constant chain ------
__global__ void __launch_bounds__(384)
k_count(int nEdgeBlocks, const int* A, const int* B,
        const float* __restrict__ W1, const float* __restrict__ W2,
        const float* __restrict__ Wout,
        const float* __restrict__ b1, const float* __restrict__ b2,
        const float* __restrict__ bout) {
    cudaTriggerProgrammaticLaunchCompletion();        // let successor prelaunch
    __shared__ int sflags[4];                         // okA, okB, zA, zB
    int t = threadIdx.x;
    if (t < 4) sflags[t] = 1;
    __syncthreads();
    if (t < 256) {
        int idx = t * 6247 + 2;                       // even, < 1,600,000
        int a0 = A[idx], a1v = A[idx + 1];
        int b0 = B[idx], b1v = B[idx + 1];
        if ((unsigned)a0 >= N_NODES || (unsigned)a1v >= N_NODES) atomicAnd(&sflags[0], 0);
        if ((unsigned)b0 >= N_NODES || (unsigned)b1v >= N_NODES) atomicAnd(&sflags[1], 0);
        if (a1v != 0) atomicAnd(&sflags[2], 0);
        if (b1v != 0) atomicAnd(&sflags[3], 0);
    }
    __syncthreads();
    const int*   ei;  int is64;  const float* feat;
    if (sflags[0] && !sflags[1]) { ei = A; is64 = sflags[2]; feat = (const float*)B; }
    else                         { ei = B; is64 = sflags[3]; feat = (const float*)A; }

    if (blockIdx.x == 0 && t == 0) {                  // publish for later kernels
        g_ei_ptr = ei; g_ei64 = is64; g_feat_p = feat;
    }

    if (blockIdx.x < (unsigned)nEdgeBlocks) {         // ---- degree pass ----
        int e = blockIdx.x * 384 + t;
        if (e >= N_EDGES) return;
        int d;
        if (is64) d = (int)((const long long*)ei)[N_EDGES + e];
        else      d = ei[N_EDGES + e];
        if ((unsigned)d >= N_NODES) return;           // guard: never trap
        atomicAdd(&g_deg[d], 1.0f);
        return;
    }

    // ---- constants block: U = W2@Wout ; Wc = W1@U ; v = b1@U ; c = b2@Wout+bout
    __shared__ float sWo[H * OUTD];
    __shared__ float sU [H * OUTD];
    sWo[t] = Wout[t];                                 // t < 384 exactly
    __syncthreads();
    {                                                  // phase 1: U
        int k = t / 3, o = t % 3;
        float s = 0.0f;
        #pragma unroll 8
        for (int j = 0; j < H; j++) s = fmaf(W2[k * H + j], sWo[j * 3 + o], s);
        sU[t] = s;
    }
    __syncthreads();
    {                                                  // phase 2: Wc
        int r = t / 3, o = t % 3;
        float s = 0.0f;
        #pragma unroll 8
        for (int k = 0; k < H; k++) s = fmaf(W1[r * H + k], sU[k * 3 + o], s);
        g_Wc[t] = s;
    }
    if (t < 3) {                                       // phase 3: v
        float s = 0.0f;
        for (int k = 0; k < H; k++) s = fmaf(b1[k], sU[k * 3 + t], s);
        g_v[t] = s;
    } else if (t < 6) {                                // phase 3: c
        int o = t - 3;
        float s = 0.0f;
        for (int j = 0; j < H; j++) s = fmaf(b2[j], sWo[j * 3 + o], s);
        g_c[o] = s + bout[o];
    }
}

// ---------------- K2: dinv + fused z via packed f32x2, p = (dinv*z, dinv) --
__global__ void __launch_bounds__(256)
k_feat(const float* __restrict__ Win, const float* __restrict__ bin) {
    cudaTriggerProgrammaticLaunchCompletion();
    __shared__ __align__(16) float sWin[DIN * H];
    __shared__ __align__(16) float sbin[H];
    __shared__ __align__(16) u64   sWc01[H];          // (Wc[j][0], Wc[j][1]) packed
    __shared__ __align__(16) float sWc2 [H];          // Wc[j][2]
    int t = threadIdx.x;
    // independent prologue (inputs only) — overlaps k_count under PDL
    for (int idx = t; idx < DIN * H; idx += blockDim.x) sWin[idx] = Win[idx];
    for (int idx = t; idx < H; idx += blockDim.x) sbin[idx] = bin[idx];

    cudaGridDependencySynchronize();                  // wait: g_Wc, g_deg, g_feat_p

    for (int j = t; j < H; j += blockDim.x) {
        sWc01[j] = pk2(g_Wc[j * 3 + 0], g_Wc[j * 3 + 1]);
        sWc2 [j] = g_Wc[j * 3 + 2];
    }
    __syncthreads();

    int i = blockIdx.x * blockDim.x + t;
    if (i >= N_NODES) return;

    float dv = rsqrtf(g_deg[i] + 1.0f);
    g_dinv[i] = dv;

    const float4* Fr = (const float4*)(g_feat_p + (size_t)i * DIN);
    float4 fa = Fr[0], fb = Fr[1], fc = Fr[2], fd = Fr[3];
    float f[16] = { fa.x, fa.y, fa.z, fa.w, fb.x, fb.y, fb.z, fb.w,
                    fc.x, fc.y, fc.z, fc.w, fd.x, fd.y, fd.z, fd.w };
    u64 ff[16];
    #pragma unroll
    for (int k = 0; k < DIN; k++) ff[k] = pk2(f[k], f[k]);

    u64  acc01 = pk2(0.0f, 0.0f);
    float acc2 = 0.0f;

    #pragma unroll 4
    for (int j0 = 0; j0 < H; j0 += 4) {
        u64 h01 = *(const u64*)&sbin[j0];
        u64 h23 = *(const u64*)&sbin[j0 + 2];
        #pragma unroll
        for (int k = 0; k < DIN; k++) {
            const u64* w = (const u64*)&sWin[k * H + j0];  // 8B-aligned (j0%4==0)
            fma2(h01, ff[k], w[0]);
            fma2(h23, ff[k], w[1]);
        }
        float h0, h1, h2, h3;
        upk2(h0, h1, h01);
        upk2(h2, h3, h23);
        // LeakyReLU: max(h,0) + SLOPE*min(h,0)  (FMNMX on alu pipe)
        h0 = fmaf(SLOPE, fminf(h0, 0.0f), fmaxf(h0, 0.0f));
        h1 = fmaf(SLOPE, fminf(h1, 0.0f), fmaxf(h1, 0.0f));
        h2 = fmaf(SLOPE, fminf(h2, 0.0f), fmaxf(h2, 0.0f));
        h3 = fmaf(SLOPE, fminf(h3, 0.0f), fmaxf(h3, 0.0f));
        // ×Wc — packed cols (0,1) + scalar col 2
        fma2(acc01, pk2(h0, h0), sWc01[j0 + 0]); acc2 = fmaf(h0, sWc2[j0 + 0], acc2);
        fma2(acc01, pk2(h1, h1), sWc01[j0 + 1]); acc2 = fmaf(h1, sWc2[j0 + 1], acc2);
        fma2(acc01, pk2(h2, h2), sWc01[j0 + 2]); acc2 = fmaf(h2, sWc2[j0 + 2], acc2);
        fma2(acc01, pk2(h3, h3), sWc01[j0 + 3]); acc2 = fmaf(h3, sWc2[j0 + 3], acc2);
    }
    float acc0, acc1;
    upk2(acc0, acc1, acc01);
    g_z4[i] = make_float4(acc0 * dv, acc1 * dv, acc2 * dv, dv);
}

// ---------------- K3: edge pass 1 — pure gather + vector atomic ------------
__global__ void k_scatter1() {
    cudaTriggerProgrammaticLaunchCompletion();
    cudaGridDependencySynchronize();
    int e = blockIdx.x * blockDim.x + threadIdx.x;
    if (e >= N_EDGES) return;
    int2 sd = load_edge_g(e);
    if ((unsigned)sd.x >= N_NODES || (unsigned)sd.y >= N_NODES) return;
    atomicAdd(&g_acc[sd.y], g_z4[sd.x]);              // acc_d += (dinv_s*z_s, dinv_s)
}

// ---------------- K4: finalize hop 1, pack q, reset acc --------------------
__global__ void k_mid() {
    cudaTriggerProgrammaticLaunchCompletion();
    cudaGridDependencySynchronize();
    int i = blockIdx.x * blockDim.x + threadIdx.x;
    if (i >= N_NODES) return;
    float dv = g_dinv[i];
    float4 acc = g_acc[i];
    float4 p   = g_z4[i];
    float z1x = dv * (acc.x + p.x);
    float z1y = dv * (acc.y + p.y);
    float z1z = dv * (acc.z + p.z);
    g_a1[i]  = dv * (acc.w + p.w);
    g_z14[i] = make_float4(dv * z1x, dv * z1y, dv * z1z, 0.0f);   // q = (dinv*z1, 0)
    g_acc[i] = make_float4(0.0f, 0.0f, 0.0f, 0.0f);               // reset for pass 2
}

// ---------------- K5: edge pass 2 — identical form -------------------------
__global__ void k_scatter2() {
    cudaTriggerProgrammaticLaunchCompletion();
    cudaGridDependencySynchronize();
    int e = blockIdx.x * blockDim.x + threadIdx.x;
    if (e >= N_EDGES) return;
    int2 sd = load_edge_g(e);
    if ((unsigned)sd.x >= N_NODES || (unsigned)sd.y >= N_NODES) return;
    atomicAdd(&g_acc[sd.y], g_z14[sd.x]);             // acc_d += (dinv_s*z1_s, 0)
}

// ---------------- K6: emit output + restore zero-state for next replay -----
__global__ void k_final(float* __restrict__ out) {
    cudaGridDependencySynchronize();
    int i = blockIdx.x * blockDim.x + threadIdx.x;
    if (i >= N_NODES) return;
    float dv = g_dinv[i];
    float4 acc = g_acc[i];
    float4 q   = g_z14[i];
    float a    = g_a1[i];
    out[3 * i + 0] = dv * (acc.x + q.x) + a * g_v[0] + g_c[0];
    out[3 * i + 1] = dv * (acc.y + q.y) + a * g_v[1] + g_c[1];
    out[3 * i + 2] = dv * (acc.z + q.z) + a * g_v[2] + g_c[2];
    g_deg[i] = 0.0f;                                  // restore invariant
    g_acc[i] = make_float4(0.0f, 0.0f, 0.0f, 0.0f);
}

// ---------------- launch (PDL on every dependent boundary) ------------------
template <typename K, typename... Args>
static inline void launch_pdl(K kernel, dim3 grid, dim3 block, bool pdl, Args... args) {
    cudaLaunchConfig_t cfg = {};
    cfg.gridDim = grid;
    cfg.blockDim = block;
    cudaLaunchAttribute attr[1];
    if (pdl) {
        attr[0].id = cudaLaunchAttributeProgrammaticStreamSerialization;
        attr[0].val.programmaticStreamSerializationAllowed = 1;
        cfg.attrs = attr;
        cfg.numAttrs = 1;
    }
    cudaLaunchKernelEx(&cfg, kernel, args...);
}

extern "C" void kernel_launch(void* const* d_in, const int* in_sizes, int n_in,
                              void* d_out, int out_size) {
    // ---- size-based scan (order-independent) ----
    const void* cand16[2] = {0, 0}; int n16 = 0;      // feature / edge_index
    const float* W16k[2]  = {0, 0}; int nW  = 0;      // 128x128 mats, in order seen
    const float* b128[3]  = {0, 0, 0}; int nb = 0;    // biases (zeros in data)
    const float* Win  = 0;
    const float* Wout = 0;
    const float* bout = 0;
    int pos3 = -1;

    for (int i = 0; i < n_in; i++) {
        switch (in_sizes[i]) {
            case 1600000: if (n16 < 2) cand16[n16++] = d_in[i]; break;
            case 800000:  /* edge_type — unused */              break;
            case 2048:    Win  = (const float*)d_in[i];         break;
            case 16384:   if (nW < 2) W16k[nW++] = (const float*)d_in[i]; break;
            case 384:     Wout = (const float*)d_in[i];         break;
            case 128:     if (nb < 3) b128[nb++] = (const float*)d_in[i]; break;
            case 3:       bout = (const float*)d_in[i]; pos3 = i; break;
            default: break;
        }
    }
    const float* W1;
    const float* W2;
    if (pos3 == 0) { W2 = W16k[0]; W1 = W16k[1]; }    // reversed-order convention
    else           { W1 = W16k[0]; W2 = W16k[1]; }
    if (n16 < 2 || nW < 2 || nb < 3 || !Win || !Wout || !bout) {   // dict-order fallback
        cand16[0] = d_in[0]; cand16[1] = d_in[1];
        Win = (const float*)d_in[3]; b128[0] = (const float*)d_in[4];
        W1  = (const float*)d_in[5]; b128[1] = (const float*)d_in[6];
        W2  = (const float*)d_in[7]; b128[2] = (const float*)d_in[8];
        Wout = (const float*)d_in[9]; bout = (const float*)d_in[10];
    }
    const float* bin = b128[0];
    const float* b1  = b128[1];
    const float* b2  = b128[2];
    float* out = (float*)d_out;

    const int TB  = 256;
    const int GN  = (N_NODES + TB - 1) / TB;           // 391
    const int GE  = (N_EDGES + TB - 1) / TB;           // 3125
    const int GE2 = (N_EDGES + 383) / 384;             // 2084 edge blocks @384

    launch_pdl(k_count, dim3(GE2 + 1), dim3(384), false,
               GE2, (const int*)cand16[0], (const int*)cand16[1],
               W1, W2, Wout, b1, b2, bout);
    launch_pdl(k_feat,     dim3(GN), dim3(TB), true, Win, bin);
    launch_pdl(k_scatter1, dim3(GE), dim3(TB), true);
    launch_pdl(k_mid,      dim3(GN), dim3(TB), true);
    launch_pdl(k_scatter2, dim3(GE), dim3(TB), true);
    launch_pdl(k_final,    dim3(GN), dim3(TB), true, out);
}

// round 16
// speedup vs baseline: 1.0464x; 1.0464x over previous
#include <cuda_runtime.h>

#define N_NODES 100000
#define N_EDGES 800000
#define DIN 16
#define H 128
#define OUTD 3
#define SLOPE 0.01f

typedef unsigned long long u64;

// ---------------- packed f32x2 helpers (sm_103a) ----------------
__device__ __forceinline__ u64 pk2(float lo, float hi) {
    u64 r; asm("mov.b64 %0, {%1, %2};" : "=l"(r) : "f"(lo), "f"(hi)); return r;
}
__device__ __forceinline__ void upk2(float& lo, float& hi, u64 v) {
    asm("mov.b64 {%0, %1}, %2;" : "=f"(lo), "=f"(hi) : "l"(v));
}
__device__ __forceinline__ void fma2(u64& d, u64 a, u64 b) {
    asm("fma.rn.f32x2 %0, %1, %2, %0;" : "+l"(d) : "l"(a), "l"(b));
}

// ---------------- scratch (no allocations; zero-initialized at load) -------
// INVARIANT: g_deg and g_acc are all-zero at kernel_launch entry; k_final
// restores this before finishing, so graph replays are deterministic.
__device__ __align__(16) float  g_deg[N_NODES];       // in-degree (float)
__device__ __align__(16) float  g_dinv[N_NODES];      // rsqrt(deg+1)
__device__ __align__(16) float4 g_z4 [N_NODES];       // p = (dinv*z, dinv)
__device__ __align__(16) float4 g_acc[N_NODES];       // edge accumulator (both passes)
__device__ __align__(16) float4 g_z14[N_NODES];       // q = (dinv*z1, 0)
__device__ __align__(16) float  g_a1 [N_NODES];       // (A·1)_d
__device__ __align__(16) float  g_Wc [H * OUTD];      // W1 @ W2 @ W_out
__device__ float g_v[OUTD];                           // b1 @ W2 @ W_out
__device__ float g_c[OUTD];                           // b2 @ W_out + b_out

// resolved by k_count block 0 (stream order = visibility for later kernels)
__device__ const void*  g_ei_ptr;                     // edge_index [2, E]
__device__ int          g_ei64;                       // 1 = int64 elements, 0 = int32
__device__ const float* g_feat_p;                     // feature    [N, DIN]

__device__ __forceinline__ int2 load_edge_g(int e) {
    if (g_ei64) {
        const long long* p = (const long long*)g_ei_ptr;
        return make_int2((int)p[e], (int)p[N_EDGES + e]);
    } else {
        const int* p = (const int*)g_ei_ptr;
        return make_int2(p[e], p[N_EDGES + e]);
    }
}

// ---------------- K1: per-block ident + degree count + constant chain ------
// ident: sample int32 WORDS (in-bounds for either dtype).
//  edge_index(int32): every word in [0, N)                      -> edge, !is64
//  edge_index(int64): words alternate (index, 0), all in [0, N) -> edge,  is64
//  feature (float32): N(0,1) bits land in [0,100000) only for |f|<1.4e-40
__global__ void __launch_bounds__(384)
k_count(int nEdgeBlocks, const int* A, const int* B,
        const float* __restrict__ W1, const float* __restrict__ W2,
        const float* __restrict__ Wout,
        const float* __restrict__ b1, const float* __restrict__ b2,
        const float* __restrict__ bout) {
    __shared__ int sflags[4];                         // okA, okB, zA, zB
    int t = threadIdx.x;
    if (t < 4) sflags[t] = 1;
    __syncthreads();
    if (t < 256) {
        int idx = t * 6247 + 2;                       // even, < 1,600,000
        int a0 = A[idx], a1v = A[idx + 1];
        int b0 = B[idx], b1v = B[idx + 1];
        if ((unsigned)a0 >= N_NODES || (unsigned)a1v >= N_NODES) atomicAnd(&sflags[0], 0);
        if ((unsigned)b0 >= N_NODES || (unsigned)b1v >= N_NODES) atomicAnd(&sflags[1], 0);
        if (a1v != 0) atomicAnd(&sflags[2], 0);
        if (b1v != 0) atomicAnd(&sflags[3], 0);
    }
    __syncthreads();
    const int*   ei;  int is64;  const float* feat;
    if (sflags[0] && !sflags[1]) { ei = A; is64 = sflags[2]; feat = (const float*)B; }
    else                         { ei = B; is64 = sflags[3]; feat = (const float*)A; }

    if (blockIdx.x == 0 && t == 0) {                  // publish for later kernels
        g_ei_ptr = ei; g_ei64 = is64; g_feat_p = feat;
    }

    if (blockIdx.x < (unsigned)nEdgeBlocks) {         // ---- degree pass ----
        int e = blockIdx.x * 384 + t;
        if (e >= N_EDGES) return;
        int d;
        if (is64) d = (int)((const long long*)ei)[N_EDGES + e];
        else      d = ei[N_EDGES + e];
        if ((unsigned)d >= N_NODES) return;           // guard: never trap
        atomicAdd(&g_deg[d], 1.0f);
        return;
    }

    // ---- constants block: U = W2@Wout ; Wc = W1@U ; v = b1@U ; c = b2@Wout+bout
    __shared__ float sWo[H * OUTD];
    __shared__ float sU [H * OUTD];
    sWo[t] = Wout[t];                                 // t < 384 exactly
    __syncthreads();
    {                                                  // phase 1: U
        int k = t / 3, o = t % 3;
        float s = 0.0f;
        #pragma unroll 8
        for (int j = 0; j < H; j++) s = fmaf(W2[k * H + j], sWo[j * 3 + o], s);
        sU[t] = s;
    }
    __syncthreads();
    {                                                  // phase 2: Wc
        int r = t / 3, o = t % 3;
        float s = 0.0f;
        #pragma unroll 8
        for (int k = 0; k < H; k++) s = fmaf(W1[r * H + k], sU[k * 3 + o], s);
        g_Wc[t] = s;
    }
    if (t < 3) {                                       // phase 3: v
        float s = 0.0f;
        for (int k = 0; k < H; k++) s = fmaf(b1[k], sU[k * 3 + t], s);
        g_v[t] = s;
    } else if (t < 6) {                                // phase 3: c
        int o = t - 3;
        float s = 0.0f;
        for (int j = 0; j < H; j++) s = fmaf(b2[j], sWo[j * 3 + o], s);
        g_c[o] = s + bout[o];
    }
}

// ---------------- K2: dinv + fused z via packed f32x2, p = (dinv*z, dinv) --
__global__ void __launch_bounds__(256)
k_feat(const float* __restrict__ Win, const float* __restrict__ bin) {
    __shared__ __align__(16) float sWin[DIN * H];
    __shared__ __align__(16) float sbin[H];
    __shared__ __align__(16) u64   sWc01[H];          // (Wc[j][0], Wc[j][1]) packed
    __shared__ __align__(16) float sWc2 [H];          // Wc[j][2]
    int t = threadIdx.x;
    for (int idx = t; idx < DIN * H; idx += blockDim.x) sWin[idx] = Win[idx];
    for (int idx = t; idx < H; idx += blockDim.x) sbin[idx] = bin[idx];
    for (int j = t; j < H; j += blockDim.x) {
        sWc01[j] = pk2(g_Wc[j * 3 + 0], g_Wc[j * 3 + 1]);
        sWc2 [j] = g_Wc[j * 3 + 2];
    }
    __syncthreads();

    int i = blockIdx.x * blockDim.x + t;
    if (i >= N_NODES) return;

    float dv = rsqrtf(g_deg[i] + 1.0f);
    g_dinv[i] = dv;

    const float4* Fr = (const float4*)(g_feat_p + (size_t)i * DIN);
    float4 fa = Fr[0], fb = Fr[1], fc = Fr[2], fd = Fr[3];
    float f[16] = { fa.x, fa.y, fa.z, fa.w, fb.x, fb.y, fb.z, fb.w,
                    fc.x, fc.y, fc.z, fc.w, fd.x, fd.y, fd.z, fd.w };
    u64 ff[16];
    #pragma unroll
    for (int k = 0; k < DIN; k++) ff[k] = pk2(f[k], f[k]);

    u64  acc01 = pk2(0.0f, 0.0f);
    float acc2 = 0.0f;

    #pragma unroll 4
    for (int j0 = 0; j0 < H; j0 += 4) {
        u64 h01 = *(const u64*)&sbin[j0];
        u64 h23 = *(const u64*)&sbin[j0 + 2];
        #pragma unroll
        for (int k = 0; k < DIN; k++) {
            const u64* w = (const u64*)&sWin[k * H + j0];  // 8B-aligned (j0%4==0)
            fma2(h01, ff[k], w[0]);
            fma2(h23, ff[k], w[1]);
        }
        float h0, h1, h2, h3;
        upk2(h0, h1, h01);
        upk2(h2, h3, h23);
        // LeakyReLU: max(h,0) + SLOPE*min(h,0)  (FMNMX on alu pipe)
        h0 = fmaf(SLOPE, fminf(h0, 0.0f), fmaxf(h0, 0.0f));
        h1 = fmaf(SLOPE, fminf(h1, 0.0f), fmaxf(h1, 0.0f));
        h2 = fmaf(SLOPE, fminf(h2, 0.0f), fmaxf(h2, 0.0f));
        h3 = fmaf(SLOPE, fminf(h3, 0.0f), fmaxf(h3, 0.0f));
        // ×Wc — packed cols (0,1) + scalar col 2
        fma2(acc01, pk2(h0, h0), sWc01[j0 + 0]); acc2 = fmaf(h0, sWc2[j0 + 0], acc2);
        fma2(acc01, pk2(h1, h1), sWc01[j0 + 1]); acc2 = fmaf(h1, sWc2[j0 + 1], acc2);
        fma2(acc01, pk2(h2, h2), sWc01[j0 + 2]); acc2 = fmaf(h2, sWc2[j0 + 2], acc2);
        fma2(acc01, pk2(h3, h3), sWc01[j0 + 3]); acc2 = fmaf(h3, sWc2[j0 + 3], acc2);
    }
    float acc0, acc1;
    upk2(acc0, acc1, acc01);
    g_z4[i] = make_float4(acc0 * dv, acc1 * dv, acc2 * dv, dv);
}

// ---------------- K3: edge pass 1 — pure gather + vector atomic ------------
__global__ void k_scatter1() {
    int e = blockIdx.x * blockDim.x + threadIdx.x;
    if (e >= N_EDGES) return;
    int2 sd = load_edge_g(e);
    if ((unsigned)sd.x >= N_NODES || (unsigned)sd.y >= N_NODES) return;
    atomicAdd(&g_acc[sd.y], g_z4[sd.x]);              // acc_d += (dinv_s*z_s, dinv_s)
}

// ---------------- K4: finalize hop 1, pack q, reset acc --------------------
// z1 = dinv*(acc.xyz + p.xyz)  (self-loop folds in);  a1 = dinv*(acc.w + p.w)
__global__ void k_mid() {
    int i = blockIdx.x * blockDim.x + threadIdx.x;
    if (i >= N_NODES) return;
    float dv = g_dinv[i];
    float4 acc = g_acc[i];
    float4 p   = g_z4[i];
    float z1x = dv * (acc.x + p.x);
    float z1y = dv * (acc.y + p.y);
    float z1z = dv * (acc.z + p.z);
    g_a1[i]  = dv * (acc.w + p.w);
    g_z14[i] = make_float4(dv * z1x, dv * z1y, dv * z1z, 0.0f);   // q = (dinv*z1, 0)
    g_acc[i] = make_float4(0.0f, 0.0f, 0.0f, 0.0f);               // reset for pass 2
}

// ---------------- K5: edge pass 2 — identical form -------------------------
__global__ void k_scatter2() {
    int e = blockIdx.x * blockDim.x + threadIdx.x;
    if (e >= N_EDGES) return;
    int2 sd = load_edge_g(e);
    if ((unsigned)sd.x >= N_NODES || (unsigned)sd.y >= N_NODES) return;
    atomicAdd(&g_acc[sd.y], g_z14[sd.x]);             // acc_d += (dinv_s*z1_s, 0)
}

// ---------------- K6: emit output + restore zero-state for next replay -----
// out = dinv*(acc.xyz + q.xyz) + a1*v + c
__global__ void k_final(float* __restrict__ out) {
    int i = blockIdx.x * blockDim.x + threadIdx.x;
    if (i >= N_NODES) return;
    float dv = g_dinv[i];
    float4 acc = g_acc[i];
    float4 q   = g_z14[i];
    float a    = g_a1[i];
    out[3 * i + 0] = dv * (acc.x + q.x) + a * g_v[0] + g_c[0];
    out[3 * i + 1] = dv * (acc.y + q.y) + a * g_v[1] + g_c[1];
    out[3 * i + 2] = dv * (acc.z + q.z) + a * g_v[2] + g_c[2];
    g_deg[i] = 0.0f;                                  // restore invariant
    g_acc[i] = make_float4(0.0f, 0.0f, 0.0f, 0.0f);
}

// ---------------- launch ----------------
extern "C" void kernel_launch(void* const* d_in, const int* in_sizes, int n_in,
                              void* d_out, int out_size) {
    // ---- size-based scan (order-independent) ----
    const void* cand16[2] = {0, 0}; int n16 = 0;      // feature / edge_index
    const float* W16k[2]  = {0, 0}; int nW  = 0;      // 128x128 mats, in order seen
    const float* b128[3]  = {0, 0, 0}; int nb = 0;    // biases (zeros in data)
    const float* Win  = 0;
    const float* Wout = 0;
    const float* bout = 0;
    int pos3 = -1;

    for (int i = 0; i < n_in; i++) {
        switch (in_sizes[i]) {
            case 1600000: if (n16 < 2) cand16[n16++] = d_in[i]; break;
            case 800000:  /* edge_type — unused */              break;
            case 2048:    Win  = (const float*)d_in[i];         break;
            case 16384:   if (nW < 2) W16k[nW++] = (const float*)d_in[i]; break;
            case 384:     Wout = (const float*)d_in[i];         break;
            case 128:     if (nb < 3) b128[nb++] = (const float*)d_in[i]; break;
            case 3:       bout = (const float*)d_in[i]; pos3 = i; break;
            default: break;
        }
    }
    const float* W1;
    const float* W2;
    if (pos3 == 0) { W2 = W16k[0]; W1 = W16k[1]; }    // reversed-order convention
    else           { W1 = W16k[0]; W2 = W16k[1]; }
    if (n16 < 2 || nW < 2 || nb < 3 || !Win || !Wout || !bout) {   // dict-order fallback
        cand16[0] = d_in[0]; cand16[1] = d_in[1];
        Win = (const float*)d_in[3]; b128[0] = (const float*)d_in[4];
        W1  = (const float*)d_in[5]; b128[1] = (const float*)d_in[6];
        W2  = (const float*)d_in[7]; b128[2] = (const float*)d_in[8];
        Wout = (const float*)d_in[9]; bout = (const float*)d_in[10];
    }
    const float* bin = b128[0];
    const float* b1  = b128[1];
    const float* b2  = b128[2];
    float* out = (float*)d_out;

    const int TB  = 256;
    const int GN  = (N_NODES + TB - 1) / TB;           // 391
    const int GE  = (N_EDGES + TB - 1) / TB;           // 3125
    const int GE2 = (N_EDGES + 383) / 384;             // 2084 edge blocks @384

    k_count<<<GE2 + 1, 384>>>(GE2, (const int*)cand16[0], (const int*)cand16[1],
                              W1, W2, Wout, b1, b2, bout);
    k_feat<<<GN, TB>>>(Win, bin);
    k_scatter1<<<GE, TB>>>();
    k_mid<<<GN, TB>>>();
    k_scatter2<<<GE, TB>>>();
    k_final<<<GN, TB>>>(out);
}